// round 3
// baseline (speedup 1.0000x reference)
#include <cuda_runtime.h>

// Input:  image [256, 384, 384] float32   (i, j, c')
// Output: out   [1, 384, 320, 512] float32 (j, a, c)
//
// c: 384 -> 512 (x4/3): outputs 4K..4K+3 <- inputs 3K-1..3K+3,
//    fixed weights {0.875, 0.625, 0.375, 0.125}
// a: 256 -> 320 (x5/4): outputs 5m..5m+4 <- rows 4m-1..4m+4,
//    fixed weights {0.9, 0.7, 0.5, 0.3, 0.1}
// Boundary clamps degenerate (x[i]==x[i+1]) so fixed weights hold everywhere.
//
// Thread k (lane) owns output cols 16k..16k+15  -> input cols 12k-1..12k+12:
// 3 aligned float4 loads + 2 warp shuffles for the edge taps.

#define D0 256
#define D1 384
#define D2 384
#define S0 320
#define S1 384
#define S2 512

__global__ __launch_bounds__(128)
void resize3d_kernel(const float* __restrict__ in, float* __restrict__ out) {
    const int k = threadIdx.x;                    // lane 0..31: c-tile
    const int m = blockIdx.x * 4 + threadIdx.y;   // a-group 0..63
    const int j = blockIdx.y;                     // 0..383

    const float* base = in + (size_t)j * D2 + 12 * k;
    const size_t rowstride = (size_t)D1 * D2;

    // c-lerp one input row (12+2 taps) into 16 outputs
    auto lerprow = [&](int i, float* l) {
        const float4* rp = (const float4*)(base + (size_t)i * rowstride);
        float4 A = __ldg(rp + 0);
        float4 B = __ldg(rp + 1);
        float4 C = __ldg(rp + 2);
        // neighbor taps via shuffle (clamp at warp edges == index clamp)
        float xm1 = __shfl_up_sync(0xffffffffu, C.w, 1);
        if (k == 0) xm1 = A.x;                    // col max(-1,0)=0
        float x12 = __shfl_down_sync(0xffffffffu, A.x, 1);
        if (k == 31) x12 = C.w;                   // col min(384,383)=383
        float x[14] = {xm1, A.x, A.y, A.z, A.w, B.x, B.y, B.z, B.w,
                       C.x, C.y, C.z, C.w, x12};
        #pragma unroll
        for (int g = 0; g < 4; ++g) {
            const float* t = x + 3 * g;           // taps t[0..4]
            l[4 * g + 0] = t[0] + 0.875f * (t[1] - t[0]);
            l[4 * g + 1] = t[1] + 0.625f * (t[2] - t[1]);
            l[4 * g + 2] = t[2] + 0.375f * (t[3] - t[2]);
            l[4 * g + 3] = t[3] + 0.125f * (t[4] - t[3]);
        }
    };

    float p[16];
    lerprow(max(4 * m - 1, 0), p);

    float4* op = (float4*)(out + ((size_t)j * S0 + 5 * m) * S2 + 16 * k);
    const float wa[5] = {0.9f, 0.7f, 0.5f, 0.3f, 0.1f};

    #pragma unroll
    for (int s = 0; s < 5; ++s) {
        float cur[16];
        lerprow(min(4 * m + s, D0 - 1), cur);
        float w = wa[s];
        float o[16];
        #pragma unroll
        for (int t = 0; t < 16; ++t)
            o[t] = p[t] + w * (cur[t] - p[t]);
        op[0] = make_float4(o[0],  o[1],  o[2],  o[3]);
        op[1] = make_float4(o[4],  o[5],  o[6],  o[7]);
        op[2] = make_float4(o[8],  o[9],  o[10], o[11]);
        op[3] = make_float4(o[12], o[13], o[14], o[15]);
        op += S2 / 4;
        #pragma unroll
        for (int t = 0; t < 16; ++t) p[t] = cur[t];
    }
}

extern "C" void kernel_launch(void* const* d_in, const int* in_sizes, int n_in,
                              void* d_out, int out_size) {
    (void)in_sizes; (void)n_in; (void)out_size;
    const float* in = (const float*)d_in[0];
    float* out = (float*)d_out;

    dim3 grid(S0 / 5 / 4, S1, 1);   // (a-group blocks, j)
    dim3 block(32, 4, 1);           // lane = c-tile, y = a-group within block
    resize3d_kernel<<<grid, block>>>(in, out);
}

// round 4
// speedup vs baseline: 1.5290x; 1.5290x over previous
#include <cuda_runtime.h>

// Input:  image [256, 384, 384] float32   (i, j, c')
// Output: out   [1, 384, 320, 512] float32 (j, a, c)
//
// c: 384 -> 512 (x4/3): outputs 4k..4k+3 <- inputs 3k-1..3k+3,
//    fixed weights {0.875, 0.625, 0.375, 0.125}
// a: 256 -> 320 (x5/4): outputs 5m..5m+4 <- rows 4m-1..4m+4,
//    fixed weights {0.9, 0.7, 0.5, 0.3, 0.1}
// Boundary clamps degenerate (x[i]==x[i+1]) so fixed weights hold everywhere.
//
// R4 structure: front-batch ALL 30 input loads (6 rows x 5 taps) before any
// compute -> max MLP; then 6 c-lerps; then 5 float4 streaming stores.

#define D0 256
#define D1 384
#define D2 384
#define S0 320
#define S1 384
#define S2 512

__global__ __launch_bounds__(128)
void resize3d_kernel(const float* __restrict__ in, float* __restrict__ out) {
    const int k = threadIdx.x;   // c-group 0..127 -> output cols 4k..4k+3
    const int m = blockIdx.x;    // a-group 0..63  -> output rows 5m..5m+4
    const int j = blockIdx.y;    // 0..383 pass-through

    // Column taps (clamped): clamp(3k-1+t, 0, 383), t=0..4
    const int col0 = max(3 * k - 1, 0);
    const int col1 = 3 * k;
    const int col4 = min(3 * k + 3, D2 - 1);

    const float* base = in + (size_t)j * D2;
    const size_t rowstride = (size_t)D1 * D2;

    // Row indices (clamped): rows 4m-1 .. 4m+4
    int ri[6];
    ri[0] = max(4 * m - 1, 0);
    ri[1] = 4 * m;
    ri[2] = 4 * m + 1;
    ri[3] = 4 * m + 2;
    ri[4] = 4 * m + 3;
    ri[5] = min(4 * m + 4, D0 - 1);

    // ---- Phase 1: issue all 30 loads (no dependent compute in between) ----
    float x[6][5];
    #pragma unroll
    for (int t = 0; t < 6; ++t) {
        const float* r = base + (size_t)ri[t] * rowstride;
        x[t][0] = __ldg(r + col0);
        x[t][1] = __ldg(r + col1);
        x[t][2] = __ldg(r + col1 + 1);
        x[t][3] = __ldg(r + col1 + 2);
        x[t][4] = __ldg(r + col4);
    }

    // ---- Phase 2: c-lerp each row into 4 values ----
    float l[6][4];
    #pragma unroll
    for (int t = 0; t < 6; ++t) {
        l[t][0] = x[t][0] + 0.875f * (x[t][1] - x[t][0]);
        l[t][1] = x[t][1] + 0.625f * (x[t][2] - x[t][1]);
        l[t][2] = x[t][2] + 0.375f * (x[t][3] - x[t][2]);
        l[t][3] = x[t][3] + 0.125f * (x[t][4] - x[t][3]);
    }

    // ---- Phase 3: a-lerp + streaming stores ----
    float4* op = (float4*)(out + ((size_t)j * S0 + 5 * m) * S2 + 4 * k);
    const float wa[5] = {0.9f, 0.7f, 0.5f, 0.3f, 0.1f};

    #pragma unroll
    for (int s = 0; s < 5; ++s) {
        float w = wa[s];
        float4 o;
        o.x = l[s][0] + w * (l[s + 1][0] - l[s][0]);
        o.y = l[s][1] + w * (l[s + 1][1] - l[s][1]);
        o.z = l[s][2] + w * (l[s + 1][2] - l[s][2]);
        o.w = l[s][3] + w * (l[s + 1][3] - l[s][3]);
        __stcs(op, o);               // evict-first: write-once output
        op += S2 / 4;
    }
}

extern "C" void kernel_launch(void* const* d_in, const int* in_sizes, int n_in,
                              void* d_out, int out_size) {
    (void)in_sizes; (void)n_in; (void)out_size;
    const float* in = (const float*)d_in[0];
    float* out = (float*)d_out;

    dim3 grid(S0 / 5, S1, 1);   // (a-groups fastest -> adjacent blocks share rows in L2, j)
    dim3 block(128, 1, 1);
    resize3d_kernel<<<grid, block>>>(in, out);
}

// round 5
// speedup vs baseline: 1.6257x; 1.0632x over previous
#include <cuda_runtime.h>

// Input:  image [256, 384, 384] float32   (i, j, c')
// Output: out   [1, 384, 320, 512] float32 (j, a, c)
//
// c: 384 -> 512 (x4/3): outputs 4k..4k+3 <- inputs 3k-1..3k+3,
//    fixed weights {0.875, 0.625, 0.375, 0.125}
// a: 256 -> 320 (x5/4): outputs 5m..5m+4 <- rows 4m-1..4m+4,
//    fixed weights {0.9, 0.7, 0.5, 0.3, 0.1}
// Boundary clamps degenerate (x[i]==x[i+1]) so fixed weights hold everywhere.
//
// R5: smem-staged. One block = (j, two a-groups m=2*m2, 2*m2+1):
//   Phase 1: 10 input rows (8*m2-1 .. 8*m2+8, clamped, deduped in smem)
//            loaded as fully-coalesced float4.
//   Phase 2: per-thread taps from smem (stride-3 cols -> conflict-free banks),
//            c-lerp + a-lerp, 5 float4 streaming stores per thread.

#define D0 256
#define D1 384
#define D2 384
#define S0 320
#define S1 384
#define S2 512

#define ROWS_SM 10          // input rows staged per block
#define THREADS 256

__global__ __launch_bounds__(THREADS)
void resize3d_kernel(const float* __restrict__ in, float* __restrict__ out) {
    __shared__ float sm[ROWS_SM][D2];

    const int tid = threadIdx.x;
    const int m2 = blockIdx.x;      // 0..31: pair of a-groups
    const int j  = blockIdx.y;      // 0..383

    // ---- Phase 1: coalesced float4 staging of 10 input rows ----
    // row t in smem <- input row clamp(8*m2 - 1 + t, 0, 255)
    {
        const int base_row = 8 * m2 - 1;
        #pragma unroll
        for (int idx = tid; idx < ROWS_SM * (D2 / 4); idx += THREADS) {
            int t = idx / (D2 / 4);
            int q = idx % (D2 / 4);
            int g = min(max(base_row + t, 0), D0 - 1);
            const float4* rp = (const float4*)(in + ((size_t)g * D1 + j) * D2);
            ((float4*)sm[t])[q] = __ldg(rp + q);
        }
    }
    __syncthreads();

    // ---- Phase 2: interpolate ----
    const int k = tid & 127;        // c-group 0..127 -> output cols 4k..4k+3
    const int y = tid >> 7;         // 0..1: which a-group of the pair
    const int m = 2 * m2 + y;

    const int col0 = max(3 * k - 1, 0);
    const int col1 = 3 * k;
    const int col4 = min(3 * k + 3, D2 - 1);
    const int t0 = 4 * y;           // smem slots t0..t0+5 hold rows 4m-1..4m+4

    float l[6][4];
    #pragma unroll
    for (int t = 0; t < 6; ++t) {
        const float* r = sm[t0 + t];
        float x0 = r[col0];
        float x1 = r[col1];
        float x2 = r[col1 + 1];
        float x3 = r[col1 + 2];
        float x4 = r[col4];
        l[t][0] = x0 + 0.875f * (x1 - x0);
        l[t][1] = x1 + 0.625f * (x2 - x1);
        l[t][2] = x2 + 0.375f * (x3 - x2);
        l[t][3] = x3 + 0.125f * (x4 - x3);
    }

    float4* op = (float4*)(out + ((size_t)j * S0 + 5 * m) * S2 + 4 * k);
    const float wa[5] = {0.9f, 0.7f, 0.5f, 0.3f, 0.1f};

    #pragma unroll
    for (int s = 0; s < 5; ++s) {
        float w = wa[s];
        float4 o;
        o.x = l[s][0] + w * (l[s + 1][0] - l[s][0]);
        o.y = l[s][1] + w * (l[s + 1][1] - l[s][1]);
        o.z = l[s][2] + w * (l[s + 1][2] - l[s][2]);
        o.w = l[s][3] + w * (l[s + 1][3] - l[s][3]);
        __stcs(op, o);
        op += S2 / 4;
    }
}

extern "C" void kernel_launch(void* const* d_in, const int* in_sizes, int n_in,
                              void* d_out, int out_size) {
    (void)in_sizes; (void)n_in; (void)out_size;
    const float* in = (const float*)d_in[0];
    float* out = (float*)d_out;

    dim3 grid(S0 / 5 / 2, S1, 1);   // (a-group pairs fastest, j)
    dim3 block(THREADS, 1, 1);
    resize3d_kernel<<<grid, block>>>(in, out);
}